// round 4
// baseline (speedup 1.0000x reference)
#include <cuda_runtime.h>
#include <cstdint>

// VQ nearest-codebook quantization, fp32-exact, using Blackwell packed
// dual-FP32 (fma.rn.f32x2) for 2x FFMA throughput.
// x: (B=16, D=64, H=64, W=64) f32, codebook: (K=1024, D=64) f32.
// Out: quantized (B,D,H,W) f32 [4194304] then indices as f32 (B,H,W) [65536].

#define TM 64      // points per block (w dimension of one (b,h))
#define TK 128     // codebook chunk resident in smem
#define DD 64
#define KTOT 1024
#define NTHREADS 256

#define PSTRIDE 132   // psd row: 128 floats (64 dup pairs) + 4 pad
#define CSTRIDE 132   // cs  row: 128 floats (codewords)    + 4 pad
#define SMEM_FLOATS (DD * PSTRIDE + DD * CSTRIDE)   // 16896 floats = 67584 B

__device__ float g_cbT[DD * KTOT];   // codebook transposed: [d][k]
__device__ float g_cnorm[KTOT];

// packed f32x2 fma: d = a * b + d  (two fp32 lanes in one 64-bit reg)
#define FMA2(d, a, b) \
    asm("fma.rn.f32x2 %0, %1, %2, %0;" : "+l"(d) : "l"(a), "l"(b))
#define UNPACK2(u0, u1, v) \
    asm("mov.b64 {%0, %1}, %2;" : "=r"(u0), "=r"(u1) : "l"(v))

// ---------------- prep: transpose codebook + norms ---------------------------
__global__ void __launch_bounds__(NTHREADS)
prep_cb(const float* __restrict__ cb) {
    int k = blockIdx.x * blockDim.x + threadIdx.x;
    if (k >= KTOT) return;
    float s = 0.f;
#pragma unroll
    for (int d4 = 0; d4 < DD; d4 += 4) {
        float4 v = *(const float4*)(cb + (size_t)k * DD + d4);
        s += v.x * v.x + v.y * v.y + v.z * v.z + v.w * v.w;
        g_cbT[(d4 + 0) * KTOT + k] = v.x;   // coalesced per d across threads
        g_cbT[(d4 + 1) * KTOT + k] = v.y;
        g_cbT[(d4 + 2) * KTOT + k] = v.z;
        g_cbT[(d4 + 3) * KTOT + k] = v.w;
    }
    g_cnorm[k] = s;
}

// ---------------- main fused kernel ------------------------------------------
__global__ void __launch_bounds__(NTHREADS, 2)
vq_kernel(const float* __restrict__ x, const float* __restrict__ cb,
          float* __restrict__ out, int write_idx) {
    extern __shared__ float smem[];
    float* psd = smem;                 // [DD][PSTRIDE] duplicated points (a,a)
    float* cs  = smem + DD * PSTRIDE;  // [DD][CSTRIDE] codeword chunk

    const int tid = threadIdx.x;
    const int bh  = blockIdx.x;        // 0..1023
    const int b = bh >> 6;
    const int h = bh & 63;

    const int tx = tid & 31;           // lane -> codewords 4*tx .. 4*tx+3 of chunk
    const int ty = tid >> 5;           // warp -> points 8*ty .. 8*ty+7

    // x[b][d][h][w]
    const float* xbase = x + (size_t)b * (DD * 4096) + (size_t)h * 64;

    // Load + duplicate point tile: psd[d][2w] = psd[d][2w+1] = x[b][d][h][w]
    for (int i = tid; i < DD * 16; i += NTHREADS) {
        int d  = i >> 4;
        int w4 = (i & 15) * 4;
        float4 v = *(const float4*)(xbase + (size_t)d * 4096 + w4);
        float* row = psd + d * PSTRIDE + 2 * w4;
        float4 lo = make_float4(v.x, v.x, v.y, v.y);
        float4 hi = make_float4(v.z, v.z, v.w, v.w);
        *(float4*)(row + 0) = lo;
        *(float4*)(row + 4) = hi;
    }

    float bestv[8];
    int   besti[8];
#pragma unroll
    for (int p = 0; p < 8; p++) { bestv[p] = 3.4e38f; besti[p] = 0; }

    const float* arow0 = psd + 16 * ty;   // 8 dup-pairs = 16 floats per warp
    const float* brow0 = cs + 4 * tx;

    for (int chunk = 0; chunk < KTOT; chunk += TK) {
        __syncthreads();  // previous iteration done reading cs
        // Codebook chunk from pre-transposed global: straight float4 copy.
        for (int i = tid; i < DD * 32; i += NTHREADS) {
            int d  = i >> 5;
            int c4 = (i & 31) * 4;
            *(float4*)(cs + d * CSTRIDE + c4) =
                *(const float4*)(g_cbT + (size_t)d * KTOT + chunk + c4);
        }
        __syncthreads();

        // acc[p][q]: point p (8), codeword-pair q (2) -> 4 codewords
        unsigned long long acc[8][2];
#pragma unroll
        for (int p = 0; p < 8; p++) { acc[p][0] = 0ull; acc[p][1] = 0ull; }

#pragma unroll 4
        for (int d = 0; d < DD; d++) {
            const ulonglong2* ar = (const ulonglong2*)(arow0 + d * PSTRIDE);
            ulonglong2 a0 = ar[0];   // dup pairs: points 0,1
            ulonglong2 a1 = ar[1];   // points 2,3
            ulonglong2 a2 = ar[2];   // points 4,5
            ulonglong2 a3 = ar[3];   // points 6,7
            ulonglong2 bb = *(const ulonglong2*)(brow0 + d * CSTRIDE);
            FMA2(acc[0][0], a0.x, bb.x); FMA2(acc[0][1], a0.x, bb.y);
            FMA2(acc[1][0], a0.y, bb.x); FMA2(acc[1][1], a0.y, bb.y);
            FMA2(acc[2][0], a1.x, bb.x); FMA2(acc[2][1], a1.x, bb.y);
            FMA2(acc[3][0], a1.y, bb.x); FMA2(acc[3][1], a1.y, bb.y);
            FMA2(acc[4][0], a2.x, bb.x); FMA2(acc[4][1], a2.x, bb.y);
            FMA2(acc[5][0], a2.y, bb.x); FMA2(acc[5][1], a2.y, bb.y);
            FMA2(acc[6][0], a3.x, bb.x); FMA2(acc[6][1], a3.x, bb.y);
            FMA2(acc[7][0], a3.y, bb.x); FMA2(acc[7][1], a3.y, bb.y);
        }

        // d2 = ||c||^2 - 2 x.c ; running argmin (ascending index order ->
        // strict < keeps first occurrence, matching jnp.argmin).
        const int c0 = chunk + 4 * tx;
        float4 nrm = __ldg((const float4*)(g_cnorm + c0));
#pragma unroll
        for (int p = 0; p < 8; p++) {
            uint32_t u0, u1, u2, u3;
            UNPACK2(u0, u1, acc[p][0]);
            UNPACK2(u2, u3, acc[p][1]);
            float d2;
            d2 = fmaf(-2.f, __uint_as_float(u0), nrm.x);
            if (d2 < bestv[p]) { bestv[p] = d2; besti[p] = c0 + 0; }
            d2 = fmaf(-2.f, __uint_as_float(u1), nrm.y);
            if (d2 < bestv[p]) { bestv[p] = d2; besti[p] = c0 + 1; }
            d2 = fmaf(-2.f, __uint_as_float(u2), nrm.z);
            if (d2 < bestv[p]) { bestv[p] = d2; besti[p] = c0 + 2; }
            d2 = fmaf(-2.f, __uint_as_float(u3), nrm.w);
            if (d2 < bestv[p]) { bestv[p] = d2; besti[p] = c0 + 3; }
        }
    }

    // Reduce argmin across the 32 lanes of the warp (same 8 points per warp).
#pragma unroll
    for (int off = 16; off > 0; off >>= 1) {
#pragma unroll
        for (int p = 0; p < 8; p++) {
            float v2 = __shfl_down_sync(0xFFFFFFFFu, bestv[p], off);
            int   c2 = __shfl_down_sync(0xFFFFFFFFu, besti[p], off);
            if (v2 < bestv[p] || (v2 == bestv[p] && c2 < besti[p])) {
                bestv[p] = v2;
                besti[p] = c2;
            }
        }
    }

    __syncthreads();  // all done with psd/cs before smem reuse
    int* bidx = (int*)smem;  // 64 ints
    if (tx == 0) {
#pragma unroll
        for (int p = 0; p < 8; p++) bidx[8 * ty + p] = besti[p];
    }
    __syncthreads();

    // Gather winning codebook rows coalesced into smem, then write transposed.
    float* tmp = smem + 128;  // [TM][68] staging
    for (int i = tid; i < TM * 16; i += NTHREADS) {
        int w  = i >> 4;
        int d4 = (i & 15) * 4;
        *(float4*)(tmp + w * 68 + d4) =
            *(const float4*)(cb + (size_t)bidx[w] * DD + d4);
    }
    __syncthreads();
    float* qbase = out + (size_t)b * (DD * 4096) + (size_t)h * 64;
    for (int i = tid; i < TM * 16; i += NTHREADS) {
        int d  = i >> 4;
        int w4 = (i & 15) * 4;
        float4 v;
        v.x = tmp[(w4 + 0) * 68 + d];
        v.y = tmp[(w4 + 1) * 68 + d];
        v.z = tmp[(w4 + 2) * 68 + d];
        v.w = tmp[(w4 + 3) * 68 + d];
        *(float4*)(qbase + (size_t)d * 4096 + w4) = v;
    }

    if (write_idx && tid < TM) {
        out[(size_t)4194304 + (size_t)bh * 64 + tid] = (float)bidx[tid];
    }
}

// ---------------- launch -----------------------------------------------------
extern "C" void kernel_launch(void* const* d_in, const int* in_sizes, int n_in,
                              void* d_out, int out_size) {
    const float* x  = (const float*)d_in[0];
    const float* cb = (const float*)d_in[1];
    if (n_in >= 2 && in_sizes[0] == KTOT * DD && in_sizes[1] == 16 * 64 * 64 * 64) {
        x  = (const float*)d_in[1];
        cb = (const float*)d_in[0];
    }
    float* out = (float*)d_out;

    const int smem_bytes = SMEM_FLOATS * (int)sizeof(float);
    cudaFuncSetAttribute(vq_kernel, cudaFuncAttributeMaxDynamicSharedMemorySize,
                         smem_bytes);

    int write_idx = (out_size >= 4194304 + 65536) ? 1 : 0;
    prep_cb<<<(KTOT + NTHREADS - 1) / NTHREADS, NTHREADS>>>(cb);
    vq_kernel<<<1024, NTHREADS, smem_bytes>>>(x, cb, out, write_idx);
}